// round 3
// baseline (speedup 1.0000x reference)
#include <cuda_runtime.h>
#include <cuda_bf16.h>

// DTW 2048x2048, anti-diagonal wavefront, 4-CTA cluster (one cluster), each
// CTA on its own SM. CTA c owns rows [512c, 512c+512): 4 warps x 32 lanes x
// 4 rows/thread. Intra-CTA warp handoff: local smem ring + acquire/release
// progress counters (R2 scheme). Cross-CTA handoff: last warp of CTA c writes
// its bottom-row value per diagonal straight into CTA c+1's ring[0] via
// mapa + st.shared::cluster, publishing a release counter per 16-diag batch;
// CTA c+1's warp 0 polls its LOCAL counter with ld.acquire.cluster.
// Backpressure: warp 0 mirrors its progress back into the upstream CTA.
//
// Cell recurrence per diagonal d, row r (4 per thread):
//   n[r] = (x[r]-y[d-i0-r])^2 + min(up, left, diag)
// with up/left/diag all in registers except each warp's top row, which takes
// 'up' from shfl_up / the ring. Out-of-range cells stay +inf (left edge) or
// finite garbage that only flows rightward (right edge) -- never into valid
// cells, so no predicates. y staged zero-padded in smem; a 4-deep
// time-indexed register queue gives 1 LDS of y per thread per step.

#define NLEN  2048
#define NC    4             // CTAs in cluster
#define NW    4             // warps per CTA
#define RPT   4             // rows per thread
#define KB    16            // diagonals per batch
#define NB    255           // full batches (255*16 = 4080)
#define TAIL  15            // 4080 + 15 = 4095 diagonals
#define SRING 64
#define FINF  __int_as_float(0x7f800000)

__device__ __forceinline__ unsigned smem_u32(const void* p) {
    return (unsigned)__cvta_generic_to_shared(p);
}
__device__ __forceinline__ unsigned mapa_u32(unsigned addr, unsigned rank) {
    unsigned r;
    asm("mapa.shared::cluster.u32 %0, %1, %2;" : "=r"(r) : "r"(addr), "r"(rank));
    return r;
}
__device__ __forceinline__ int ld_acq_cluster(const int* p) {
    int v; unsigned a = smem_u32(p);
    asm volatile("ld.acquire.cluster.shared::cta.b32 %0, [%1];" : "=r"(v) : "r"(a) : "memory");
    return v;
}
__device__ __forceinline__ void st_rel_cta(int* p, int v) {
    unsigned a = smem_u32(p);
    asm volatile("st.release.cta.shared::cta.b32 [%0], %1;" :: "r"(a), "r"(v) : "memory");
}
__device__ __forceinline__ void st_rel_cluster_rem(unsigned a, int v) {
    asm volatile("st.release.cluster.shared::cluster.b32 [%0], %1;" :: "r"(a), "r"(v) : "memory");
}
__device__ __forceinline__ void st_f32_rem(unsigned a, float v) {
    asm volatile("st.shared::cluster.f32 [%0], %1;" :: "r"(a), "f"(v) : "memory");
}
__device__ __forceinline__ void cluster_sync_() {
    asm volatile("barrier.cluster.arrive.aligned;" ::: "memory");
    asm volatile("barrier.cluster.wait.aligned;" ::: "memory");
}
__device__ __forceinline__ unsigned ctarank_() {
    unsigned r; asm("mov.u32 %0, %%cluster_ctarank;" : "=r"(r)); return r;
}

__global__ __launch_bounds__(NW * 32, 1) __cluster_dims__(NC, 1, 1)
void dtw_cluster_kernel(const float* __restrict__ x,
                        const float* __restrict__ y,
                        float* __restrict__ out)
{
    __shared__ float ysp[3 * NLEN];         // ysp[NLEN + j] = y[j], pads = 0
    __shared__ float ring[NW + 1][SRING];   // ring[0]: from upstream CTA (or +inf)
    __shared__ int   prog[NW + 2];          // [0]=upstream, [1..NW]=local warps, [NW+1]=downstream

    const int t    = threadIdx.x;
    const int lane = t & 31;
    const int w    = t >> 5;
    const unsigned rank = ctarank_();       // == blockIdx.x (single cluster)
    const bool has_prev = (rank != 0);
    const bool has_next = (rank != NC - 1);

    for (int k = t; k < 3 * NLEN; k += NW * 32) {
        int j = k - NLEN;
        ysp[k] = ((unsigned)j < (unsigned)NLEN) ? y[j] : 0.0f;
    }
    for (int k = t; k < (NW + 1) * SRING; k += NW * 32)
        (&ring[0][0])[k] = FINF;
    if (t < NW + 2) {
        int v = -1;
        if (t == 0      && !has_prev) v = 0x7fffffff;   // no upstream producer
        if (t == NW + 1 && !has_next) v = 0x7fffffff;   // no downstream consumer
        prog[t] = v;
    }

    const int i0 = (int)rank * 512 + w * 128 + lane * RPT;   // top row of this thread

    float xv[RPT];
    {
        float4 a = reinterpret_cast<const float4*>(x + i0)[0];
        xv[0] = a.x; xv[1] = a.y; xv[2] = a.z; xv[3] = a.w;
    }

    float p[RPT], pp[RPT], yq[RPT];
    #pragma unroll
    for (int r = 0; r < RPT; ++r) { p[r] = FINF; pp[r] = FINF; }
    float dTop = (rank == 0 && t == 0) ? 0.0f : FINF;   // virtual DTW[-1][-1]=0 seeds (0,0)

    // Remote addresses (computed once).
    unsigned rem_ring0 = 0, rem_prog0 = 0, rem_progN1 = 0;
    if (w == NW - 1 && has_next) {
        rem_ring0 = mapa_u32(smem_u32(&ring[0][0]), rank + 1);
        rem_prog0 = mapa_u32(smem_u32(&prog[0]),    rank + 1);
    }
    if (w == 0 && has_prev) {
        rem_progN1 = mapa_u32(smem_u32(&prog[NW + 1]), rank - 1);
    }

    cluster_sync_();   // smem init (rings/counters) visible cluster-wide

    const float* yb = ysp + NLEN - i0;      // yb[d] = y[d - i0] (zero padded)
    yq[3] = yb[-1]; yq[2] = yb[-2]; yq[1] = yb[-3];   // steps -1..-3

    const float* ringprev = ring[w];
    float*       ringself = ring[w + 1];
    const bool   last_warp = (w == NW - 1);

    for (int m = 0; m <= NB; ++m) {
        const int d0    = m * KB;
        const int steps = (m == NB) ? TAIL : KB;
        const int need1 = d0 + steps - 2;                 // producer done through here
        const int need2 = d0 + steps - 1 - (SRING - 1);   // consumer read ring this far
        int v1, v2;
        do { v1 = ld_acq_cluster(prog + w); v2 = ld_acq_cluster(prog + w + 2); }
        while (v1 < need1 || v2 < need2);

        const float* ybb = yb + d0;
        float*       rs  = ringself + (d0 & (SRING - 1));    // no wrap within a batch
        const float* rpb = ringprev + (d0 & (SRING - 1));
        const unsigned rrs = rem_ring0 + (unsigned)((d0 & (SRING - 1)) << 2);
        const float  up_first = ringprev[(d0 - 1) & (SRING - 1)];

        #pragma unroll
        for (int u = 0; u < KB; ++u) {
            if (u >= steps) break;   // trims only the tail batch
            const float yn = ybb[u];
            yq[u & 3] = yn;
            float up = __shfl_up_sync(0xffffffffu, p[RPT - 1], 1);
            if (lane == 0) up = (u == 0) ? up_first : rpb[u - 1];

            float nv[RPT];
            {
                const float dy = xv[0] - yn;
                nv[0] = fmaf(dy, dy, fminf(fminf(up, dTop), p[0]));
            }
            #pragma unroll
            for (int r = 1; r < RPT; ++r) {
                const float dy = xv[r] - yq[(u - r) & 3];
                nv[r] = fmaf(dy, dy, fminf(fminf(p[r - 1], pp[r - 1]), p[r]));
            }

            if (lane == 31) {
                if (!last_warp)      rs[u] = nv[RPT - 1];
                else if (has_next)   st_f32_rem(rrs + (unsigned)(u << 2), nv[RPT - 1]);
            }

            dTop = up;
            #pragma unroll
            for (int r = 0; r < RPT; ++r) { pp[r] = p[r]; p[r] = nv[r]; }
        }

        const int done = d0 + steps - 1;
        if (lane == 31) {
            st_rel_cta(prog + w + 1, done);                     // local consumer/producer checks
            if (last_warp && has_next) st_rel_cluster_rem(rem_prog0, done);   // notify downstream
            if (w == 0 && has_prev)    st_rel_cluster_rem(rem_progN1, done);  // backpressure upstream
        }
    }

    // Global last row 2047 lives in CTA 3, warp NW-1, lane 31, r=3.
    if (!has_next && t == NW * 32 - 1) out[0] = sqrtf(p[RPT - 1]);

    cluster_sync_();   // no CTA exits while peers may still write into its smem
}

extern "C" void kernel_launch(void* const* d_in, const int* in_sizes, int n_in,
                              void* d_out, int out_size)
{
    const float* x = (const float*)d_in[0];
    const float* y = (const float*)d_in[1];
    float* out = (float*)d_out;
    dtw_cluster_kernel<<<NC, NW * 32>>>(x, y, out);
}